// round 2
// baseline (speedup 1.0000x reference)
#include <cuda_runtime.h>

// ---------------------------------------------------------------------------
// GCNConv: out[row] += (dinv[row]*dinv[col]) * (x@W)[col]  over edges + self loops
// Inputs (metadata order): x [N,128] f32, W [128,128] f32, edge_index [2,E] int64-or-int32,
//                          num_nodes (scalar, ignored; N derived from x)
// Output: out [N,128] f32
// ---------------------------------------------------------------------------

#define MAXN 131072
#define C 128

__device__ __align__(16) float g_h[(size_t)MAXN * C];   // h = x @ W
__device__ float g_deg[MAXN];
__device__ float g_dinv[MAXN];
__device__ int   g_is64;

// --- detect whether edge_index buffer is int64 or int32 -------------------
__global__ void detect_k(const unsigned long long* p) {
    int ok = 1;
    #pragma unroll 1
    for (int i = 0; i < 64; i++) {
        if ((p[i] >> 32) != 0ULL) ok = 0;
    }
    g_is64 = ok;
}

__device__ __forceinline__ int eidx(const void* ei, long long i, int is64) {
    if (is64) return (int)(((const long long*)ei)[i]);
    return ((const int*)ei)[i];
}

// --- degree init: self loop contributes 1 to every node --------------------
__global__ void init_deg_k(int N) {
    int i = blockIdx.x * blockDim.x + threadIdx.x;
    if (i < N) g_deg[i] = 1.0f;
}

// --- degree count on col ----------------------------------------------------
__global__ void deg_k(const void* __restrict__ ei, int E) {
    int is64 = g_is64;
    int stride = gridDim.x * blockDim.x;
    for (int e = blockIdx.x * blockDim.x + threadIdx.x; e < E; e += stride) {
        int c = eidx(ei, (long long)E + e, is64);
        atomicAdd(&g_deg[c], 1.0f);
    }
}

// --- dinv = rsqrt(deg); deg >= 1 always (self loops) -----------------------
__global__ void dinv_k(int N) {
    int i = blockIdx.x * blockDim.x + threadIdx.x;
    if (i < N) g_dinv[i] = rsqrtf(g_deg[i]);
}

// --- SGEMM h = x @ W : M x 128 x 128, BM=64, BK=32, 256 thr, 4x8 microtile --
__global__ void gemm_k(const float* __restrict__ x, const float* __restrict__ W, int M) {
    __shared__ __align__(16) float As[64][33];
    __shared__ __align__(16) float Bs[32][128];

    int tid = threadIdx.x;
    int tx = tid & 15;   // col group: 8 cols
    int ty = tid >> 4;   // row group: 4 rows
    int m0 = blockIdx.x * 64;

    float acc[4][8];
    #pragma unroll
    for (int i = 0; i < 4; i++)
        #pragma unroll
        for (int j = 0; j < 8; j++) acc[i][j] = 0.0f;

    #pragma unroll 1
    for (int k0 = 0; k0 < 128; k0 += 32) {
        // load A tile 64x32 (512 float4s, 2 per thread)
        #pragma unroll
        for (int s = 0; s < 2; s++) {
            int f = tid + s * 256;
            int row = f >> 3;
            int c4 = f & 7;
            int gr = m0 + row;
            float4 v = make_float4(0.f, 0.f, 0.f, 0.f);
            if (gr < M) v = *(const float4*)(x + (long long)gr * C + k0 + c4 * 4);
            As[row][c4 * 4 + 0] = v.x;
            As[row][c4 * 4 + 1] = v.y;
            As[row][c4 * 4 + 2] = v.z;
            As[row][c4 * 4 + 3] = v.w;
        }
        // load B tile 32x128 (1024 float4s, 4 per thread)
        #pragma unroll
        for (int s = 0; s < 4; s++) {
            int f = tid + s * 256;
            int row = f >> 5;
            int c4 = f & 31;
            *(float4*)&Bs[row][c4 * 4] = *(const float4*)(W + (k0 + row) * C + c4 * 4);
        }
        __syncthreads();

        #pragma unroll
        for (int k = 0; k < 32; k++) {
            float a[4];
            a[0] = As[ty * 4 + 0][k];
            a[1] = As[ty * 4 + 1][k];
            a[2] = As[ty * 4 + 2][k];
            a[3] = As[ty * 4 + 3][k];
            float4 b0 = *(const float4*)&Bs[k][tx * 8];
            float4 b1 = *(const float4*)&Bs[k][tx * 8 + 4];
            float b[8] = {b0.x, b0.y, b0.z, b0.w, b1.x, b1.y, b1.z, b1.w};
            #pragma unroll
            for (int i = 0; i < 4; i++)
                #pragma unroll
                for (int j = 0; j < 8; j++)
                    acc[i][j] += a[i] * b[j];
        }
        __syncthreads();
    }

    #pragma unroll
    for (int i = 0; i < 4; i++) {
        int gr = m0 + ty * 4 + i;
        if (gr < M) {
            float* hp = g_h + (long long)gr * C + tx * 8;
            *(float4*)hp       = make_float4(acc[i][0], acc[i][1], acc[i][2], acc[i][3]);
            *(float4*)(hp + 4) = make_float4(acc[i][4], acc[i][5], acc[i][6], acc[i][7]);
        }
    }
}

// --- self-loop initializes out: out[n] = dinv[n]^2 * h[n] -------------------
__global__ void selfloop_k(float4* __restrict__ out, int N) {
    long long i = (long long)blockIdx.x * blockDim.x + threadIdx.x;  // over N*32 float4s
    if (i >= (long long)N * 32) return;
    int n = (int)(i >> 5);
    float d = g_dinv[n];
    float s = d * d;
    float4 v = ((const float4*)g_h)[i];
    out[i] = make_float4(s * v.x, s * v.y, s * v.z, s * v.w);
}

// --- edge scatter: one warp per edge, 128-bit vector RED -------------------
__device__ __forceinline__ void red_add_v4(float* p, float a, float b, float c, float d) {
    asm volatile("red.global.add.v4.f32 [%0], {%1, %2, %3, %4};"
                 :: "l"(p), "f"(a), "f"(b), "f"(c), "f"(d)
                 : "memory");
}

__global__ void scatter_k(const void* __restrict__ ei, float* __restrict__ out, int E) {
    int gt = blockIdx.x * blockDim.x + threadIdx.x;
    int e = gt >> 5;
    int lane = gt & 31;
    if (e >= E) return;
    int is64 = g_is64;
    int r = eidx(ei, e, is64);
    int c = eidx(ei, (long long)E + e, is64);
    float norm = g_dinv[r] * g_dinv[c];
    float4 v = *(const float4*)(g_h + ((long long)c << 7) + (lane << 2));
    float* p = out + ((long long)r << 7) + (lane << 2);
    red_add_v4(p, norm * v.x, norm * v.y, norm * v.z, norm * v.w);
}

// ---------------------------------------------------------------------------
extern "C" void kernel_launch(void* const* d_in, const int* in_sizes, int n_in,
                              void* d_out, int out_size) {
    const float* x = (const float*)d_in[0];
    const float* W = (const float*)d_in[1];
    const void*  ei = d_in[2];

    int N = in_sizes[0] / C;          // x is [N,128]
    int E = in_sizes[2] / 2;          // edge_index is [2,E]

    detect_k<<<1, 1>>>((const unsigned long long*)ei);

    init_deg_k<<<(N + 255) / 256, 256>>>(N);
    deg_k<<<1024, 256>>>(ei, E);
    dinv_k<<<(N + 255) / 256, 256>>>(N);

    gemm_k<<<(N + 63) / 64, 256>>>(x, W, N);

    long long sl_threads = (long long)N * 32;
    selfloop_k<<<(int)((sl_threads + 255) / 256), 256>>>((float4*)d_out, N);

    long long sc_threads = (long long)E * 32;
    scatter_k<<<(int)((sc_threads + 255) / 256), 256>>>(ei, (float*)d_out, E);
}

// round 3
// speedup vs baseline: 1.4682x; 1.4682x over previous
#include <cuda_runtime.h>

// ---------------------------------------------------------------------------
// GCNConv via CSR two-pass (no atomics in the accumulate):
//   1. histogram: rowcnt[row]++, colcnt[col]++    (one pass over edge_index)
//   2. exclusive scan rowcnt -> off, cursor
//   3. dinv = rsqrt(colcnt + 1)                   (+1 = self loop)
//   4. fill: packed[cursor[row]++] = (col, norm=dinv[row]*dinv[col])
//   5. gemm: h = x @ W
//   6. gather: out[n] = dinv[n]^2*h[n] + sum_j norm_j * h[col_j]   (warp/node)
// ---------------------------------------------------------------------------

#define MAXN 131072
#define MAXE 2097152
#define C 128

__device__ __align__(16) float g_h[(size_t)MAXN * C];       // h = x @ W
__device__ int   g_rowcnt[MAXN];
__device__ int   g_colcnt[MAXN];
__device__ float g_dinv[MAXN];
__device__ int   g_off[MAXN + 1];
__device__ int   g_cursor[MAXN];
__device__ int   g_blocksum[256];
__device__ unsigned long long g_packed[MAXE];               // (normbits<<32)|col
__device__ int   g_is64;

// --- detect whether edge_index buffer is int64 or int32 --------------------
__global__ void detect_k(const unsigned long long* p) {
    int ok = 1;
    #pragma unroll 1
    for (int i = 0; i < 64; i++)
        if ((p[i] >> 32) != 0ULL) ok = 0;
    g_is64 = ok;
}

__device__ __forceinline__ int eidx(const void* ei, long long i, int is64) {
    if (is64) return (int)(((const long long*)ei)[i]);
    return ((const int*)ei)[i];
}

// --- zero counters ----------------------------------------------------------
__global__ void zero_k(int N) {
    int i = blockIdx.x * blockDim.x + threadIdx.x;
    if (i < N) { g_rowcnt[i] = 0; g_colcnt[i] = 0; }
}

// --- histogram: row counts (CSR) and col counts (degree) --------------------
__global__ void hist_k(const void* __restrict__ ei, int E) {
    int is64 = g_is64;
    int stride = gridDim.x * blockDim.x;
    for (int e = blockIdx.x * blockDim.x + threadIdx.x; e < E; e += stride) {
        int r = eidx(ei, e, is64);
        int c = eidx(ei, (long long)E + e, is64);
        atomicAdd(&g_rowcnt[r], 1);
        atomicAdd(&g_colcnt[c], 1);
    }
}

// --- dinv = rsqrt(colcnt + 1) -----------------------------------------------
__global__ void dinv_k(int N) {
    int i = blockIdx.x * blockDim.x + threadIdx.x;
    if (i < N) g_dinv[i] = rsqrtf((float)(g_colcnt[i] + 1));
}

// --- scan stage 1: per-block (1024 elems) exclusive scan + block total ------
__global__ void scan1_k(int N) {
    __shared__ int s[1024];
    int i = blockIdx.x * 1024 + threadIdx.x;
    int v = (i < N) ? g_rowcnt[i] : 0;
    s[threadIdx.x] = v;
    __syncthreads();
    #pragma unroll
    for (int off = 1; off < 1024; off <<= 1) {
        int t = (threadIdx.x >= off) ? s[threadIdx.x - off] : 0;
        __syncthreads();
        s[threadIdx.x] += t;
        __syncthreads();
    }
    if (i < N) g_off[i] = s[threadIdx.x] - v;     // exclusive within block
    if (threadIdx.x == 1023) g_blocksum[blockIdx.x] = s[1023];
}

// --- scan stage 2: serial scan of block totals (nb <= 128, trivial) --------
__global__ void scan2_k(int nb) {
    if (threadIdx.x == 0) {
        int acc = 0;
        for (int b = 0; b < nb; b++) {
            int t = g_blocksum[b];
            g_blocksum[b] = acc;
            acc += t;
        }
    }
}

// --- scan stage 3: add block offsets, init cursor, set off[N] ---------------
__global__ void scan3_k(int N, int E) {
    int i = blockIdx.x * blockDim.x + threadIdx.x;
    if (i < N) {
        int o = g_off[i] + g_blocksum[i >> 10];
        g_off[i] = o;
        g_cursor[i] = o;
    }
    if (i == 0) g_off[N] = E;
}

// --- fill CSR: packed (col, norm) per edge ----------------------------------
__global__ void fill_k(const void* __restrict__ ei, int E) {
    int is64 = g_is64;
    int stride = gridDim.x * blockDim.x;
    for (int e = blockIdx.x * blockDim.x + threadIdx.x; e < E; e += stride) {
        int r = eidx(ei, e, is64);
        int c = eidx(ei, (long long)E + e, is64);
        float norm = g_dinv[r] * g_dinv[c];
        int pos = atomicAdd(&g_cursor[r], 1);
        g_packed[pos] = ((unsigned long long)__float_as_uint(norm) << 32) |
                        (unsigned int)c;
    }
}

// --- SGEMM h = x @ W : M x 128 x 128, BM=64, BK=32, 256 thr, 4x8 microtile --
__global__ void gemm_k(const float* __restrict__ x, const float* __restrict__ W, int M) {
    __shared__ __align__(16) float As[64][33];
    __shared__ __align__(16) float Bs[32][128];

    int tid = threadIdx.x;
    int tx = tid & 15;
    int ty = tid >> 4;
    int m0 = blockIdx.x * 64;

    float acc[4][8];
    #pragma unroll
    for (int i = 0; i < 4; i++)
        #pragma unroll
        for (int j = 0; j < 8; j++) acc[i][j] = 0.0f;

    #pragma unroll 1
    for (int k0 = 0; k0 < 128; k0 += 32) {
        #pragma unroll
        for (int s = 0; s < 2; s++) {
            int f = tid + s * 256;
            int row = f >> 3;
            int c4 = f & 7;
            int gr = m0 + row;
            float4 v = make_float4(0.f, 0.f, 0.f, 0.f);
            if (gr < M) v = *(const float4*)(x + (long long)gr * C + k0 + c4 * 4);
            As[row][c4 * 4 + 0] = v.x;
            As[row][c4 * 4 + 1] = v.y;
            As[row][c4 * 4 + 2] = v.z;
            As[row][c4 * 4 + 3] = v.w;
        }
        #pragma unroll
        for (int s = 0; s < 4; s++) {
            int f = tid + s * 256;
            int row = f >> 5;
            int c4 = f & 31;
            *(float4*)&Bs[row][c4 * 4] = *(const float4*)(W + (k0 + row) * C + c4 * 4);
        }
        __syncthreads();

        #pragma unroll
        for (int k = 0; k < 32; k++) {
            float a[4];
            a[0] = As[ty * 4 + 0][k];
            a[1] = As[ty * 4 + 1][k];
            a[2] = As[ty * 4 + 2][k];
            a[3] = As[ty * 4 + 3][k];
            float4 b0 = *(const float4*)&Bs[k][tx * 8];
            float4 b1 = *(const float4*)&Bs[k][tx * 8 + 4];
            float b[8] = {b0.x, b0.y, b0.z, b0.w, b1.x, b1.y, b1.z, b1.w};
            #pragma unroll
            for (int i = 0; i < 4; i++)
                #pragma unroll
                for (int j = 0; j < 8; j++)
                    acc[i][j] += a[i] * b[j];
        }
        __syncthreads();
    }

    #pragma unroll
    for (int i = 0; i < 4; i++) {
        int gr = m0 + ty * 4 + i;
        if (gr < M) {
            float* hp = g_h + (long long)gr * C + tx * 8;
            *(float4*)hp       = make_float4(acc[i][0], acc[i][1], acc[i][2], acc[i][3]);
            *(float4*)(hp + 4) = make_float4(acc[i][4], acc[i][5], acc[i][6], acc[i][7]);
        }
    }
}

// --- gather: one warp per node; acc init = self loop; single store ----------
__global__ void gather_k(float4* __restrict__ out, int N) {
    int warp = (blockIdx.x * blockDim.x + threadIdx.x) >> 5;
    int lane = threadIdx.x & 31;
    if (warp >= N) return;
    int n = warp;

    int beg = g_off[n];
    int end = g_off[n + 1];
    float d = g_dinv[n];
    float s = d * d;

    const float4* h4 = (const float4*)g_h;
    float4 v = h4[((long long)n << 5) + lane];
    float4 acc = make_float4(s * v.x, s * v.y, s * v.z, s * v.w);

    #pragma unroll 2
    for (int j = beg; j < end; j++) {
        unsigned long long p = g_packed[j];
        int c = (int)(unsigned int)p;
        float norm = __uint_as_float((unsigned int)(p >> 32));
        float4 hv = h4[((long long)c << 5) + lane];
        acc.x += norm * hv.x;
        acc.y += norm * hv.y;
        acc.z += norm * hv.z;
        acc.w += norm * hv.w;
    }
    out[((long long)n << 5) + lane] = acc;
}

// ---------------------------------------------------------------------------
extern "C" void kernel_launch(void* const* d_in, const int* in_sizes, int n_in,
                              void* d_out, int out_size) {
    const float* x = (const float*)d_in[0];
    const float* W = (const float*)d_in[1];
    const void*  ei = d_in[2];

    int N = in_sizes[0] / C;
    int E = in_sizes[2] / 2;

    detect_k<<<1, 1>>>((const unsigned long long*)ei);

    zero_k<<<(N + 255) / 256, 256>>>(N);
    hist_k<<<1024, 256>>>(ei, E);
    dinv_k<<<(N + 255) / 256, 256>>>(N);

    int nb = (N + 1023) / 1024;
    scan1_k<<<nb, 1024>>>(N);
    scan2_k<<<1, 32>>>(nb);
    scan3_k<<<(N + 255) / 256, 256>>>(N, E);

    fill_k<<<1024, 256>>>(ei, E);

    gemm_k<<<(N + 63) / 64, 256>>>(x, W, N);

    long long gt = (long long)N * 32;
    gather_k<<<(int)((gt + 255) / 256), 256>>>((float4*)d_out, N);
}

// round 5
// speedup vs baseline: 2.0099x; 1.3690x over previous
#include <cuda_runtime.h>
#include <cuda_bf16.h>
#include <cstdint>

// ---------------------------------------------------------------------------
// GCNConv: CSR two-pass aggregate + bf16x3-split mma.sync GEMM for h = x @ W.
// (sm_100 plain target: no tcgen05; legacy HMMA path via mma.sync.)
// ---------------------------------------------------------------------------

#define MAXN 131072
#define MAXE 2097152
#define C 128

__device__ __align__(16) float g_h[(size_t)MAXN * C];       // h = x @ W
__device__ __align__(16) __nv_bfloat16 g_wthi[C * C];       // W^T hi limb [n][k]
__device__ __align__(16) __nv_bfloat16 g_wtlo[C * C];       // W^T lo limb [n][k]
__device__ int   g_rowcnt[MAXN];
__device__ int   g_colcnt[MAXN];
__device__ float g_dinv[MAXN];
__device__ int   g_off[MAXN + 1];
__device__ int   g_cursor[MAXN];
__device__ int   g_blocksum[256];
__device__ unsigned long long g_packed[MAXE];               // (normbits<<32)|col
__device__ int   g_is64;

// ======================= small kernels ======================================
__global__ void detect_k(const unsigned long long* p) {
    int ok = 1;
    #pragma unroll 1
    for (int i = 0; i < 64; i++)
        if ((p[i] >> 32) != 0ULL) ok = 0;
    g_is64 = ok;
}

__device__ __forceinline__ int eidx(const void* ei, long long i, int is64) {
    if (is64) return (int)(((const long long*)ei)[i]);
    return ((const int*)ei)[i];
}

__global__ void zero_k(int N) {
    int i = blockIdx.x * blockDim.x + threadIdx.x;
    if (i < N) { g_rowcnt[i] = 0; g_colcnt[i] = 0; }
}

__global__ void hist_k(const void* __restrict__ ei, int E) {
    int is64 = g_is64;
    int stride = gridDim.x * blockDim.x;
    for (int e = blockIdx.x * blockDim.x + threadIdx.x; e < E; e += stride) {
        int r = eidx(ei, e, is64);
        int c = eidx(ei, (long long)E + e, is64);
        atomicAdd(&g_rowcnt[r], 1);
        atomicAdd(&g_colcnt[c], 1);
    }
}

__global__ void dinv_k(int N) {
    int i = blockIdx.x * blockDim.x + threadIdx.x;
    if (i < N) g_dinv[i] = rsqrtf((float)(g_colcnt[i] + 1));
}

__global__ void scan1_k(int N) {
    __shared__ int s[1024];
    int i = blockIdx.x * 1024 + threadIdx.x;
    int v = (i < N) ? g_rowcnt[i] : 0;
    s[threadIdx.x] = v;
    __syncthreads();
    #pragma unroll
    for (int off = 1; off < 1024; off <<= 1) {
        int t = (threadIdx.x >= off) ? s[threadIdx.x - off] : 0;
        __syncthreads();
        s[threadIdx.x] += t;
        __syncthreads();
    }
    if (i < N) g_off[i] = s[threadIdx.x] - v;
    if (threadIdx.x == 1023) g_blocksum[blockIdx.x] = s[1023];
}

__global__ void scan2_k(int nb) {
    if (threadIdx.x == 0) {
        int acc = 0;
        for (int b = 0; b < nb; b++) {
            int t = g_blocksum[b];
            g_blocksum[b] = acc;
            acc += t;
        }
    }
}

__global__ void scan3_k(int N, int E) {
    int i = blockIdx.x * blockDim.x + threadIdx.x;
    if (i < N) {
        int o = g_off[i] + g_blocksum[i >> 10];
        g_off[i] = o;
        g_cursor[i] = o;
    }
    if (i == 0) g_off[N] = E;
}

__global__ void fill_k(const void* __restrict__ ei, int E) {
    int is64 = g_is64;
    int stride = gridDim.x * blockDim.x;
    for (int e = blockIdx.x * blockDim.x + threadIdx.x; e < E; e += stride) {
        int r = eidx(ei, e, is64);
        int c = eidx(ei, (long long)E + e, is64);
        float norm = g_dinv[r] * g_dinv[c];
        int pos = atomicAdd(&g_cursor[r], 1);
        g_packed[pos] = ((unsigned long long)__float_as_uint(norm) << 32) |
                        (unsigned int)c;
    }
}

// --- transpose + bf16-split W -> g_wthi/g_wtlo [n][k] -----------------------
__global__ void wsplit_k(const float* __restrict__ W) {
    __shared__ float tile[32][33];
    int bx = blockIdx.x & 3, by = blockIdx.x >> 2;
    int tx = threadIdx.x & 31, ty = threadIdx.x >> 5;
    #pragma unroll
    for (int s = 0; s < 4; s++) {
        int k = by * 32 + ty + s * 8;
        int n = bx * 32 + tx;
        tile[ty + s * 8][tx] = W[k * C + n];
    }
    __syncthreads();
    #pragma unroll
    for (int s = 0; s < 4; s++) {
        int n = bx * 32 + ty + s * 8;
        int k = by * 32 + tx;
        float v = tile[tx][ty + s * 8];
        __nv_bfloat16 hi = __float2bfloat16_rn(v);
        __nv_bfloat16 lo = __float2bfloat16_rn(v - __bfloat162float(hi));
        g_wthi[n * C + k] = hi;
        g_wtlo[n * C + k] = lo;
    }
}

// ======================= bf16x3 mma.sync GEMM ===============================
// Per CTA: 128 rows of x, full K=128, full N=128.
// smem: xhi/xlo [128][136] bf16, whi/wlo [128][136] bf16 (rows padded to
// 272B = 17*16B so LDSM rows land in distinct 16B banks).
static constexpr int SM_STRIDE = 136;                 // bf16 elems per row
static constexpr int SM_ARR = 128 * SM_STRIDE * 2;    // 34816 bytes
static constexpr int SM_XHI = 0;
static constexpr int SM_XLO = SM_ARR;
static constexpr int SM_WHI = 2 * SM_ARR;
static constexpr int SM_WLO = 3 * SM_ARR;
static constexpr int SM_TOTAL = 4 * SM_ARR;           // 139264 bytes

__device__ __forceinline__ uint32_t smem_u32(const void* p) {
    uint32_t a;
    asm("{ .reg .u64 t; cvta.to.shared.u64 t, %1; cvt.u32.u64 %0, t; }"
        : "=r"(a) : "l"(p));
    return a;
}

#define LDSM_X4(r, addr) \
    asm volatile("ldmatrix.sync.aligned.m8n8.x4.shared.b16 {%0,%1,%2,%3}, [%4];" \
        : "=r"((r)[0]), "=r"((r)[1]), "=r"((r)[2]), "=r"((r)[3]) : "r"(addr))

#define MMA_BF16(c, a, b0, b1) \
    asm volatile("mma.sync.aligned.m16n8k16.row.col.f32.bf16.bf16.f32 " \
        "{%0,%1,%2,%3}, {%4,%5,%6,%7}, {%8,%9}, {%0,%1,%2,%3};" \
        : "+f"((c)[0]), "+f"((c)[1]), "+f"((c)[2]), "+f"((c)[3]) \
        : "r"((a)[0]), "r"((a)[1]), "r"((a)[2]), "r"((a)[3]), "r"(b0), "r"(b1))

__global__ void __launch_bounds__(256) gemm_bf16x3_k(const float* __restrict__ x, int M) {
    extern __shared__ char sm[];
    int tid = threadIdx.x;
    int wid = tid >> 5;
    int lane = tid & 31;
    int wm = wid >> 2;           // 0..1 -> m offset wm*64
    int wn = wid & 3;            // 0..3 -> n offset wn*32
    int m0 = blockIdx.x * 128;

    // --- stage x tile: read f32, split to bf16 hi/lo ---
    #pragma unroll 4
    for (int idx = tid; idx < 128 * 32; idx += 256) {
        int row = idx >> 5;
        int c4 = idx & 31;
        int gr = m0 + row;
        float4 v = make_float4(0.f, 0.f, 0.f, 0.f);
        if (gr < M) v = *(const float4*)(x + (size_t)gr * C + c4 * 4);
        __nv_bfloat16 hx = __float2bfloat16_rn(v.x);
        __nv_bfloat16 hy = __float2bfloat16_rn(v.y);
        __nv_bfloat16 hz = __float2bfloat16_rn(v.z);
        __nv_bfloat16 hw = __float2bfloat16_rn(v.w);
        __nv_bfloat16 lx = __float2bfloat16_rn(v.x - __bfloat162float(hx));
        __nv_bfloat16 ly = __float2bfloat16_rn(v.y - __bfloat162float(hy));
        __nv_bfloat16 lz = __float2bfloat16_rn(v.z - __bfloat162float(hz));
        __nv_bfloat16 lw = __float2bfloat16_rn(v.w - __bfloat162float(hw));
        size_t off = ((size_t)row * SM_STRIDE + c4 * 4) * 2;
        *(__nv_bfloat162*)(sm + SM_XHI + off)     = __nv_bfloat162(hx, hy);
        *(__nv_bfloat162*)(sm + SM_XHI + off + 4) = __nv_bfloat162(hz, hw);
        *(__nv_bfloat162*)(sm + SM_XLO + off)     = __nv_bfloat162(lx, ly);
        *(__nv_bfloat162*)(sm + SM_XLO + off + 4) = __nv_bfloat162(lz, lw);
    }
    // --- stage W tiles (already split, [n][k] bf16): 16B copies ---
    #pragma unroll 4
    for (int idx = tid; idx < 128 * 16; idx += 256) {
        int row = idx >> 4;
        int q = idx & 15;
        size_t soff = ((size_t)row * SM_STRIDE + q * 8) * 2;
        *(uint4*)(sm + SM_WHI + soff) = *(const uint4*)(g_wthi + row * C + q * 8);
        *(uint4*)(sm + SM_WLO + soff) = *(const uint4*)(g_wtlo + row * C + q * 8);
    }
    __syncthreads();

    // --- per-lane LDSM base addresses ---
    uint32_t base = smem_u32(sm);
    int sel = lane >> 3;
    int l8 = lane & 7;
    // A (16x16 tile, row-major): m0:rows0-7/k0, m1:rows8-15/k0, m2:rows0-7/k8, m3:rows8-15/k8
    int a_row = l8 + ((sel & 1) << 3);
    int a_kof = (sel >> 1) << 3;
    // B (16 n x 16 k in [n][k]): r0:n0-7/k0, r1:n0-7/k8, r2:n8-15/k0, r3:n8-15/k8
    int b_row = l8 + ((sel >> 1) << 3);
    int b_kof = (sel & 1) << 3;

    uint32_t a_addr[4], b_addr[2];
    #pragma unroll
    for (int i = 0; i < 4; i++)
        a_addr[i] = base + ((uint32_t)((wm * 64 + i * 16 + a_row) * SM_STRIDE + a_kof) << 1);
    #pragma unroll
    for (int j2 = 0; j2 < 2; j2++)
        b_addr[j2] = base + SM_WHI +
                     ((uint32_t)((wn * 32 + j2 * 16 + b_row) * SM_STRIDE + b_kof) << 1);

    float c[4][4][4];
    #pragma unroll
    for (int i = 0; i < 4; i++)
        #pragma unroll
        for (int j = 0; j < 4; j++)
            #pragma unroll
            for (int r = 0; r < 4; r++) c[i][j][r] = 0.f;

    // --- mainloop: 8 k-steps of 16 ---
    #pragma unroll 1
    for (int ks = 0; ks < 8; ks++) {
        uint32_t ko = (uint32_t)ks * 32;  // 16 bf16 = 32 bytes
        uint32_t ahi[4][4], alo[4][4], bhi[2][4], blo[2][4];
        #pragma unroll
        for (int i = 0; i < 4; i++) {
            LDSM_X4(ahi[i], a_addr[i] + ko);
            LDSM_X4(alo[i], a_addr[i] + ko + SM_ARR);
        }
        #pragma unroll
        for (int j2 = 0; j2 < 2; j2++) {
            LDSM_X4(bhi[j2], b_addr[j2] + ko);
            LDSM_X4(blo[j2], b_addr[j2] + ko + SM_ARR);
        }
        #pragma unroll
        for (int i = 0; i < 4; i++) {
            #pragma unroll
            for (int j = 0; j < 4; j++) {
                int j2 = j >> 1;
                int rb = (j & 1) << 1;
                MMA_BF16(c[i][j], ahi[i], bhi[j2][rb], bhi[j2][rb + 1]);
                MMA_BF16(c[i][j], ahi[i], blo[j2][rb], blo[j2][rb + 1]);
                MMA_BF16(c[i][j], alo[i], bhi[j2][rb], bhi[j2][rb + 1]);
            }
        }
    }

    // --- epilogue: write g_h ---
    int g = lane >> 2;
    int tg = lane & 3;
    #pragma unroll
    for (int i = 0; i < 4; i++) {
        int row0 = m0 + wm * 64 + i * 16 + g;
        #pragma unroll
        for (int j = 0; j < 4; j++) {
            int col = wn * 32 + j * 8 + tg * 2;
            if (row0 < M)
                *(float2*)(g_h + (size_t)row0 * C + col) = make_float2(c[i][j][0], c[i][j][1]);
            if (row0 + 8 < M)
                *(float2*)(g_h + (size_t)(row0 + 8) * C + col) = make_float2(c[i][j][2], c[i][j][3]);
        }
    }
}

// ======================= gather =============================================
__global__ void gather_k(float4* __restrict__ out, int N) {
    int warp = (blockIdx.x * blockDim.x + threadIdx.x) >> 5;
    int lane = threadIdx.x & 31;
    if (warp >= N) return;
    int n = warp;

    int beg = g_off[n];
    int end = g_off[n + 1];
    float d = g_dinv[n];
    float s = d * d;

    const float4* h4 = (const float4*)g_h;
    float4 v = h4[((long long)n << 5) + lane];
    float4 acc = make_float4(s * v.x, s * v.y, s * v.z, s * v.w);

    #pragma unroll 2
    for (int j = beg; j < end; j++) {
        unsigned long long p = g_packed[j];
        int c = (int)(unsigned int)p;
        float norm = __uint_as_float((unsigned int)(p >> 32));
        float4 hv = h4[((long long)c << 5) + lane];
        acc.x += norm * hv.x;
        acc.y += norm * hv.y;
        acc.z += norm * hv.z;
        acc.w += norm * hv.w;
    }
    out[((long long)n << 5) + lane] = acc;
}

// ---------------------------------------------------------------------------
extern "C" void kernel_launch(void* const* d_in, const int* in_sizes, int n_in,
                              void* d_out, int out_size) {
    const float* x = (const float*)d_in[0];
    const float* W = (const float*)d_in[1];
    const void*  ei = d_in[2];

    int N = in_sizes[0] / C;
    int E = in_sizes[2] / 2;

    cudaFuncSetAttribute(gemm_bf16x3_k, cudaFuncAttributeMaxDynamicSharedMemorySize,
                         SM_TOTAL);

    detect_k<<<1, 1>>>((const unsigned long long*)ei);

    zero_k<<<(N + 255) / 256, 256>>>(N);
    hist_k<<<1024, 256>>>(ei, E);
    dinv_k<<<(N + 255) / 256, 256>>>(N);

    int nb = (N + 1023) / 1024;
    scan1_k<<<nb, 1024>>>(N);
    scan2_k<<<1, 32>>>(nb);
    scan3_k<<<(N + 255) / 256, 256>>>(N, E);

    fill_k<<<1024, 256>>>(ei, E);

    wsplit_k<<<16, 256>>>(W);
    gemm_bf16x3_k<<<(N + 127) / 128, 256, SM_TOTAL>>>(x, N);

    long long gt = (long long)N * 32;
    gather_k<<<(int)((gt + 255) / 256), 256>>>((float4*)d_out, N);
}

// round 6
// speedup vs baseline: 2.1222x; 1.0559x over previous
#include <cuda_runtime.h>
#include <cuda_bf16.h>
#include <cuda_fp16.h>
#include <cstdint>

// ---------------------------------------------------------------------------
// GCNConv: CSR two-pass aggregate (fp16 h messages, fp32 accumulate)
//          + bf16x3-split mma.sync GEMM for h = x @ W.
// ---------------------------------------------------------------------------

#define MAXN 131072
#define MAXE 2097152
#define C 128

__device__ __align__(16) __half g_hh[(size_t)MAXN * C];     // h = x @ W (fp16)
__device__ __align__(16) __nv_bfloat16 g_wthi[C * C];       // W^T hi limb [n][k]
__device__ __align__(16) __nv_bfloat16 g_wtlo[C * C];       // W^T lo limb [n][k]
__device__ int   g_rowcnt[MAXN];
__device__ int   g_colcnt[MAXN];
__device__ float g_dinv[MAXN];
__device__ int   g_off[MAXN + 1];
__device__ int   g_cursor[MAXN];
__device__ int   g_blocksum[256];
__device__ unsigned long long g_packed[MAXE];               // (normbits<<32)|col
__device__ int   g_is64;

// ======================= small kernels ======================================
__global__ void detect_k(const unsigned long long* p) {
    int ok = 1;
    #pragma unroll 1
    for (int i = 0; i < 64; i++)
        if ((p[i] >> 32) != 0ULL) ok = 0;
    g_is64 = ok;
}

__device__ __forceinline__ int eidx(const void* ei, long long i, int is64) {
    if (is64) return (int)(((const long long*)ei)[i]);
    return ((const int*)ei)[i];
}

__global__ void zero_k(int N) {
    int i = blockIdx.x * blockDim.x + threadIdx.x;
    if (i < N) { g_rowcnt[i] = 0; g_colcnt[i] = 0; }
}

__global__ void hist_k(const void* __restrict__ ei, int E) {
    int is64 = g_is64;
    int stride = gridDim.x * blockDim.x;
    for (int e = blockIdx.x * blockDim.x + threadIdx.x; e < E; e += stride) {
        int r = eidx(ei, e, is64);
        int c = eidx(ei, (long long)E + e, is64);
        atomicAdd(&g_rowcnt[r], 1);
        atomicAdd(&g_colcnt[c], 1);
    }
}

__global__ void dinv_k(int N) {
    int i = blockIdx.x * blockDim.x + threadIdx.x;
    if (i < N) g_dinv[i] = rsqrtf((float)(g_colcnt[i] + 1));
}

__global__ void scan1_k(int N) {
    __shared__ int s[1024];
    int i = blockIdx.x * 1024 + threadIdx.x;
    int v = (i < N) ? g_rowcnt[i] : 0;
    s[threadIdx.x] = v;
    __syncthreads();
    #pragma unroll
    for (int off = 1; off < 1024; off <<= 1) {
        int t = (threadIdx.x >= off) ? s[threadIdx.x - off] : 0;
        __syncthreads();
        s[threadIdx.x] += t;
        __syncthreads();
    }
    if (i < N) g_off[i] = s[threadIdx.x] - v;
    if (threadIdx.x == 1023) g_blocksum[blockIdx.x] = s[1023];
}

__global__ void scan2_k(int nb) {
    if (threadIdx.x == 0) {
        int acc = 0;
        for (int b = 0; b < nb; b++) {
            int t = g_blocksum[b];
            g_blocksum[b] = acc;
            acc += t;
        }
    }
}

__global__ void scan3_k(int N, int E) {
    int i = blockIdx.x * blockDim.x + threadIdx.x;
    if (i < N) {
        int o = g_off[i] + g_blocksum[i >> 10];
        g_off[i] = o;
        g_cursor[i] = o;
    }
    if (i == 0) g_off[N] = E;
}

__global__ void fill_k(const void* __restrict__ ei, int E) {
    int is64 = g_is64;
    int stride = gridDim.x * blockDim.x;
    for (int e = blockIdx.x * blockDim.x + threadIdx.x; e < E; e += stride) {
        int r = eidx(ei, e, is64);
        int c = eidx(ei, (long long)E + e, is64);
        float norm = g_dinv[r] * g_dinv[c];
        int pos = atomicAdd(&g_cursor[r], 1);
        g_packed[pos] = ((unsigned long long)__float_as_uint(norm) << 32) |
                        (unsigned int)c;
    }
}

// --- transpose + bf16-split W -> g_wthi/g_wtlo [n][k] -----------------------
__global__ void wsplit_k(const float* __restrict__ W) {
    __shared__ float tile[32][33];
    int bx = blockIdx.x & 3, by = blockIdx.x >> 2;
    int tx = threadIdx.x & 31, ty = threadIdx.x >> 5;
    #pragma unroll
    for (int s = 0; s < 4; s++) {
        int k = by * 32 + ty + s * 8;
        int n = bx * 32 + tx;
        tile[ty + s * 8][tx] = W[k * C + n];
    }
    __syncthreads();
    #pragma unroll
    for (int s = 0; s < 4; s++) {
        int n = bx * 32 + ty + s * 8;
        int k = by * 32 + tx;
        float v = tile[tx][ty + s * 8];
        __nv_bfloat16 hi = __float2bfloat16_rn(v);
        __nv_bfloat16 lo = __float2bfloat16_rn(v - __bfloat162float(hi));
        g_wthi[n * C + k] = hi;
        g_wtlo[n * C + k] = lo;
    }
}

// ======================= bf16x3 mma.sync GEMM ===============================
static constexpr int SM_STRIDE = 136;                 // bf16 elems per row
static constexpr int SM_ARR = 128 * SM_STRIDE * 2;    // 34816 bytes
static constexpr int SM_XHI = 0;
static constexpr int SM_XLO = SM_ARR;
static constexpr int SM_WHI = 2 * SM_ARR;
static constexpr int SM_WLO = 3 * SM_ARR;
static constexpr int SM_TOTAL = 4 * SM_ARR;           // 139264 bytes

__device__ __forceinline__ uint32_t smem_u32(const void* p) {
    uint32_t a;
    asm("{ .reg .u64 t; cvta.to.shared.u64 t, %1; cvt.u32.u64 %0, t; }"
        : "=r"(a) : "l"(p));
    return a;
}

#define LDSM_X4(r, addr) \
    asm volatile("ldmatrix.sync.aligned.m8n8.x4.shared.b16 {%0,%1,%2,%3}, [%4];" \
        : "=r"((r)[0]), "=r"((r)[1]), "=r"((r)[2]), "=r"((r)[3]) : "r"(addr))

#define MMA_BF16(c, a, b0, b1) \
    asm volatile("mma.sync.aligned.m16n8k16.row.col.f32.bf16.bf16.f32 " \
        "{%0,%1,%2,%3}, {%4,%5,%6,%7}, {%8,%9}, {%0,%1,%2,%3};" \
        : "+f"((c)[0]), "+f"((c)[1]), "+f"((c)[2]), "+f"((c)[3]) \
        : "r"((a)[0]), "r"((a)[1]), "r"((a)[2]), "r"((a)[3]), "r"(b0), "r"(b1))

__global__ void __launch_bounds__(256) gemm_bf16x3_k(const float* __restrict__ x, int M) {
    extern __shared__ char sm[];
    int tid = threadIdx.x;
    int wid = tid >> 5;
    int lane = tid & 31;
    int wm = wid >> 2;           // 0..1 -> m offset wm*64
    int wn = wid & 3;            // 0..3 -> n offset wn*32
    int m0 = blockIdx.x * 128;

    // --- stage x tile: read f32, split to bf16 hi/lo ---
    #pragma unroll 4
    for (int idx = tid; idx < 128 * 32; idx += 256) {
        int row = idx >> 5;
        int c4 = idx & 31;
        int gr = m0 + row;
        float4 v = make_float4(0.f, 0.f, 0.f, 0.f);
        if (gr < M) v = *(const float4*)(x + (size_t)gr * C + c4 * 4);
        __nv_bfloat16 hx = __float2bfloat16_rn(v.x);
        __nv_bfloat16 hy = __float2bfloat16_rn(v.y);
        __nv_bfloat16 hz = __float2bfloat16_rn(v.z);
        __nv_bfloat16 hw = __float2bfloat16_rn(v.w);
        __nv_bfloat16 lx = __float2bfloat16_rn(v.x - __bfloat162float(hx));
        __nv_bfloat16 ly = __float2bfloat16_rn(v.y - __bfloat162float(hy));
        __nv_bfloat16 lz = __float2bfloat16_rn(v.z - __bfloat162float(hz));
        __nv_bfloat16 lw = __float2bfloat16_rn(v.w - __bfloat162float(hw));
        size_t off = ((size_t)row * SM_STRIDE + c4 * 4) * 2;
        *(__nv_bfloat162*)(sm + SM_XHI + off)     = __nv_bfloat162(hx, hy);
        *(__nv_bfloat162*)(sm + SM_XHI + off + 4) = __nv_bfloat162(hz, hw);
        *(__nv_bfloat162*)(sm + SM_XLO + off)     = __nv_bfloat162(lx, ly);
        *(__nv_bfloat162*)(sm + SM_XLO + off + 4) = __nv_bfloat162(lz, lw);
    }
    // --- stage W tiles (already split, [n][k] bf16): 16B copies ---
    #pragma unroll 4
    for (int idx = tid; idx < 128 * 16; idx += 256) {
        int row = idx >> 4;
        int q = idx & 15;
        size_t soff = ((size_t)row * SM_STRIDE + q * 8) * 2;
        *(uint4*)(sm + SM_WHI + soff) = *(const uint4*)(g_wthi + row * C + q * 8);
        *(uint4*)(sm + SM_WLO + soff) = *(const uint4*)(g_wtlo + row * C + q * 8);
    }
    __syncthreads();

    // --- per-lane LDSM base addresses ---
    uint32_t base = smem_u32(sm);
    int sel = lane >> 3;
    int l8 = lane & 7;
    int a_row = l8 + ((sel & 1) << 3);
    int a_kof = (sel >> 1) << 3;
    int b_row = l8 + ((sel >> 1) << 3);
    int b_kof = (sel & 1) << 3;

    uint32_t a_addr[4], b_addr[2];
    #pragma unroll
    for (int i = 0; i < 4; i++)
        a_addr[i] = base + ((uint32_t)((wm * 64 + i * 16 + a_row) * SM_STRIDE + a_kof) << 1);
    #pragma unroll
    for (int j2 = 0; j2 < 2; j2++)
        b_addr[j2] = base + SM_WHI +
                     ((uint32_t)((wn * 32 + j2 * 16 + b_row) * SM_STRIDE + b_kof) << 1);

    float c[4][4][4];
    #pragma unroll
    for (int i = 0; i < 4; i++)
        #pragma unroll
        for (int j = 0; j < 4; j++)
            #pragma unroll
            for (int r = 0; r < 4; r++) c[i][j][r] = 0.f;

    // --- mainloop: 8 k-steps of 16 ---
    #pragma unroll 1
    for (int ks = 0; ks < 8; ks++) {
        uint32_t ko = (uint32_t)ks * 32;
        uint32_t ahi[4][4], alo[4][4], bhi[2][4], blo[2][4];
        #pragma unroll
        for (int i = 0; i < 4; i++) {
            LDSM_X4(ahi[i], a_addr[i] + ko);
            LDSM_X4(alo[i], a_addr[i] + ko + SM_ARR);
        }
        #pragma unroll
        for (int j2 = 0; j2 < 2; j2++) {
            LDSM_X4(bhi[j2], b_addr[j2] + ko);
            LDSM_X4(blo[j2], b_addr[j2] + ko + SM_ARR);
        }
        #pragma unroll
        for (int i = 0; i < 4; i++) {
            #pragma unroll
            for (int j = 0; j < 4; j++) {
                int j2 = j >> 1;
                int rb = (j & 1) << 1;
                MMA_BF16(c[i][j], ahi[i], bhi[j2][rb], bhi[j2][rb + 1]);
                MMA_BF16(c[i][j], ahi[i], blo[j2][rb], blo[j2][rb + 1]);
                MMA_BF16(c[i][j], alo[i], bhi[j2][rb], bhi[j2][rb + 1]);
            }
        }
    }

    // --- epilogue: write g_hh (fp16) ---
    int g = lane >> 2;
    int tg = lane & 3;
    #pragma unroll
    for (int i = 0; i < 4; i++) {
        int row0 = m0 + wm * 64 + i * 16 + g;
        #pragma unroll
        for (int j = 0; j < 4; j++) {
            int col = wn * 32 + j * 8 + tg * 2;
            if (row0 < M) {
                __half2 v01 = __floats2half2_rn(c[i][j][0], c[i][j][1]);
                *(__half2*)(g_hh + (size_t)row0 * C + col) = v01;
            }
            if (row0 + 8 < M) {
                __half2 v23 = __floats2half2_rn(c[i][j][2], c[i][j][3]);
                *(__half2*)(g_hh + (size_t)(row0 + 8) * C + col) = v23;
            }
        }
    }
}

// ======================= gather (fp16 h, fp32 accumulate) ===================
__global__ void gather_k(float4* __restrict__ out, int N) {
    int warp = (blockIdx.x * blockDim.x + threadIdx.x) >> 5;
    int lane = threadIdx.x & 31;
    if (warp >= N) return;
    int n = warp;

    int beg = g_off[n];
    int end = g_off[n + 1];
    float d = g_dinv[n];
    float s = d * d;

    const uint2* h2 = (const uint2*)g_hh;   // 32 uint2 (8B = 4 halfs) per node row
    uint2 raw = h2[((size_t)n << 5) + lane];
    float2 f0 = __half22float2(*(__half2*)&raw.x);
    float2 f1 = __half22float2(*(__half2*)&raw.y);
    float4 acc = make_float4(s * f0.x, s * f0.y, s * f1.x, s * f1.y);

    #pragma unroll 4
    for (int j = beg; j < end; j++) {
        unsigned long long p = g_packed[j];
        int c = (int)(unsigned int)p;
        float norm = __uint_as_float((unsigned int)(p >> 32));
        uint2 rv = h2[((size_t)c << 5) + lane];
        float2 g0 = __half22float2(*(__half2*)&rv.x);
        float2 g1 = __half22float2(*(__half2*)&rv.y);
        acc.x += norm * g0.x;
        acc.y += norm * g0.y;
        acc.z += norm * g1.x;
        acc.w += norm * g1.y;
    }
    out[((size_t)n << 5) + lane] = acc;
}

// ---------------------------------------------------------------------------
extern "C" void kernel_launch(void* const* d_in, const int* in_sizes, int n_in,
                              void* d_out, int out_size) {
    const float* x = (const float*)d_in[0];
    const float* W = (const float*)d_in[1];
    const void*  ei = d_in[2];

    int N = in_sizes[0] / C;
    int E = in_sizes[2] / 2;

    cudaFuncSetAttribute(gemm_bf16x3_k, cudaFuncAttributeMaxDynamicSharedMemorySize,
                         SM_TOTAL);

    detect_k<<<1, 1>>>((const unsigned long long*)ei);

    zero_k<<<(N + 255) / 256, 256>>>(N);
    hist_k<<<1024, 256>>>(ei, E);
    dinv_k<<<(N + 255) / 256, 256>>>(N);

    int nb = (N + 1023) / 1024;
    scan1_k<<<nb, 1024>>>(N);
    scan2_k<<<1, 32>>>(nb);
    scan3_k<<<(N + 255) / 256, 256>>>(N, E);

    fill_k<<<1024, 256>>>(ei, E);

    wsplit_k<<<16, 256>>>(W);
    gemm_bf16x3_k<<<(N + 127) / 128, 256, SM_TOTAL>>>(x, N);

    long long gt = (long long)N * 32;
    gather_k<<<(int)((gt + 255) / 256), 256>>>((float4*)d_out, N);
}